// round 17
// baseline (speedup 1.0000x reference)
#include <cuda_runtime.h>
#include <cuda_bf16.h>
#include <cstdint>
#include <cstddef>

// Problem dims
#define B_ 8
#define L_ 1024
#define N_ 4096
#define D_ 1024
#define SCALE_F 0.03125f   // 1/sqrt(1024)/TEMPERATURE

// GEMM tiling: 128x128 tile, fp8 operands, fill granularity K=64 (64B rows)
#define BM 128
#define BN 128
#define FILLS 16                      // 1024 / 64
#define NTILES (N_ / BN)              // 32

// NOTE: deliberately ZERO module-scope __device__ data (a nonzero module data
// segment triggers a fixed 128 MiB arena on this stack -> allocation guard).

// ---------------- PTX helpers (base ISA; fp8 mma is sm_89+ base) ----------
__device__ __forceinline__ uint32_t smem_u32(const void* p) {
    uint32_t a;
    asm("{ .reg .u64 t; cvta.to.shared.u64 t, %1; cvt.u32.u64 %0, t; }"
        : "=r"(a) : "l"(p));
    return a;
}

__device__ __forceinline__ void sts8(uint32_t addr, uint32_t u0, uint32_t u1) {
    asm volatile("st.shared.v2.b32 [%0], {%1,%2};" :: "r"(addr), "r"(u0), "r"(u1));
}

__device__ __forceinline__ uint32_t lds32(uint32_t addr) {
    uint32_t v;
    asm volatile("ld.shared.b32 %0, [%1];" : "=r"(v) : "r"(addr));
    return v;
}

// m16n8k32 e4m3 MMA, fp32 accum
__device__ __forceinline__ void mma_fp8(float* c, const uint32_t* a, const uint32_t* b) {
    asm volatile(
        "mma.sync.aligned.m16n8k32.row.col.f32.e4m3.e4m3.f32 "
        "{%0,%1,%2,%3}, {%4,%5,%6,%7}, {%8,%9}, {%0,%1,%2,%3};"
        : "+f"(c[0]), "+f"(c[1]), "+f"(c[2]), "+f"(c[3])
        : "r"(a[0]), "r"(a[1]), "r"(a[2]), "r"(a[3]), "r"(b[0]), "r"(b[1]));
}

// pack float4 -> 4x e4m3 in one word (byte0 = .x ... byte3 = .w)
__device__ __forceinline__ uint32_t pack_e4m3(const float4& v) {
    uint16_t lo, hi;
    asm("cvt.rn.satfinite.e4m3x2.f32 %0, %1, %2;" : "=h"(lo) : "f"(v.y), "f"(v.x));
    asm("cvt.rn.satfinite.e4m3x2.f32 %0, %1, %2;" : "=h"(hi) : "f"(v.w), "f"(v.z));
    uint32_t r;
    asm("mov.b32 %0, {%1, %2};" : "=r"(r) : "h"(lo), "h"(hi));
    return r;
}
__device__ __forceinline__ float sumsq4(const float4& v) {
    return v.x * v.x + v.y * v.y + v.z * v.z + v.w * v.w;
}

// ============================================================================
// Kernel 0: tiny pad (capture-slot alignment)
// ============================================================================
__global__ void pad_kernel(void) {}

// ============================================================================
// Kernel 1: zero the s_ia output region (d_out is poisoned to 0xAA).
// ============================================================================
__global__ void __launch_bounds__(256) zero_sia_kernel(float* __restrict__ out) {
    int idx = blockIdx.x * 256 + threadIdx.x;
    if (idx < B_ * N_) out[idx] = 0.0f;
}

// ============================================================================
// Kernel 2: fused GEMM + norm + exp with e4m3 operands, zero global scratch.
// Round-16 profile: L1=82.8% binding. fp8 halves operand smem bytes AND
// tensor time (m16n8k32). Fragments loaded via conflict-free ld.shared.b32
// (unified swizzle sw = ((lq>>1)&3)*16; 8 rows -> distinct 16B slots mod 128).
// Direct LDG fp32 -> pack e4m3 -> STS; per-thread row sum-of-squares gives
// exact fp32 norms; bilinearity applies rinvA*rinvB*scale in the epilogue.
// e4m3 quantization => logit abs err ~1e-4*scale-class; A rel err ~1e-4 << 1e-3.
// 8 warps: 4(M) x 2(N); warp tile 32x64; 16 fills x (2 k32 MMA steps).
// ============================================================================
__global__ void __launch_bounds__(256, 2) gemm_exp_kernel(
    float* __restrict__ outA,
    const float4* __restrict__ text, const float4* __restrict__ visual) {
    __shared__ __align__(128) unsigned char smA[2][BM * 64];   // 2 x 8 KB fp8
    __shared__ __align__(128) unsigned char smB[2][BN * 64];   // 2 x 8 KB fp8
    __shared__ float sRA[BM];
    __shared__ float sRB[BN];
    const uint32_t aBuf0 = smem_u32(&smA[0][0]);
    const uint32_t aBuf1 = smem_u32(&smA[1][0]);
    const uint32_t bBuf0 = smem_u32(&smB[0][0]);
    const uint32_t bBuf1 = smem_u32(&smB[1][0]);

    const int tid = threadIdx.x;
    const int wid = tid >> 5, lane = tid & 31;
    const int nt = blockIdx.x, mt = blockIdx.y, b = blockIdx.z;
    const int m0 = mt * BM, n0 = nt * BN;
    const int wm = (wid & 3) * 32;       // warp M offset
    const int wnIdx = wid >> 2;
    const int wn = wnIdx * 64;           // warp N offset

    // ---- loader: 2 threads per row; each owns 32 fp32 (8 float4) per fill ----
    const int r = tid >> 1;              // 0..127
    const int h = tid & 1;
    const float4* gA = text   + ((size_t)(b * L_ + m0 + r)) * 256 + h * 8;
    const float4* gB = visual + ((size_t)(b * N_ + n0 + r)) * 256 + h * 8;
    const uint32_t swL = (uint32_t)((r >> 1) & 3) * 16;
    // STS addr for phase p (16 fp8 bytes = chunk 2h+p): two sts8 at +0,+8
    const uint32_t stP0 = (uint32_t)r * 64 + (((uint32_t)(2 * h + 0) * 16) ^ swL);
    const uint32_t stP1 = (uint32_t)r * 64 + (((uint32_t)(2 * h + 1) * 16) ^ swL);

    float c[2][8][4];
#pragma unroll
    for (int t = 0; t < 2; t++)
#pragma unroll
        for (int n = 0; n < 8; n++)
#pragma unroll
            for (int j = 0; j < 4; j++) c[t][n][j] = 0.0f;

    float ssA = 0.f, ssB = 0.f;

    // ---- prologue: fill 0 ----
#pragma unroll
    for (int p = 0; p < 2; p++) {
        float4 v0 = gA[p * 4 + 0], v1 = gA[p * 4 + 1],
               v2 = gA[p * 4 + 2], v3 = gA[p * 4 + 3];
        ssA += sumsq4(v0) + sumsq4(v1) + sumsq4(v2) + sumsq4(v3);
        uint32_t ad = aBuf0 + (p ? stP1 : stP0);
        sts8(ad, pack_e4m3(v0), pack_e4m3(v1));
        sts8(ad + 8, pack_e4m3(v2), pack_e4m3(v3));
    }
#pragma unroll
    for (int p = 0; p < 2; p++) {
        float4 v0 = gB[p * 4 + 0], v1 = gB[p * 4 + 1],
               v2 = gB[p * 4 + 2], v3 = gB[p * 4 + 3];
        ssB += sumsq4(v0) + sumsq4(v1) + sumsq4(v2) + sumsq4(v3);
        uint32_t ad = bBuf0 + (p ? stP1 : stP0);
        sts8(ad, pack_e4m3(v0), pack_e4m3(v1));
        sts8(ad + 8, pack_e4m3(v2), pack_e4m3(v3));
    }
    __syncthreads();

    // ---- per-lane fragment constants ----
    const int lq = lane >> 2;            // 0..7
    const int lr = lane & 3;
    const uint32_t swF = (uint32_t)((lq >> 1) & 3) * 16;     // unified swizzle
    const uint32_t aBase = (uint32_t)(wm + lq) * 64 + lr * 4;
    const uint32_t bBase = (uint32_t)(wn + lq) * 64 + lr * 4;

    for (int f = 0; f < FILLS; f++) {
        const uint32_t aC = (f & 1) ? aBuf1 : aBuf0;
        const uint32_t bC = (f & 1) ? bBuf1 : bBuf0;
        const uint32_t aN = (f & 1) ? aBuf0 : aBuf1;
        const uint32_t bN = (f & 1) ? bBuf0 : bBuf1;
        const bool more = (f + 1 < FILLS);
        const int kf = (f + 1) * 16;

        uint32_t aF0[4], aF1[4], bF[4][2];
        float4 v0, v1, v2, v3;

        // ======== k32 step s=0 (chunks 0,1) ========
        const uint32_t cA0 = (0u * 16) ^ swF, cB0 = (1u * 16) ^ swF;
        // sub0: LDG A phase0; A-frags + B-frags(j 0..3); 8 MMAs
        if (more) { v0 = gA[kf]; v1 = gA[kf + 1]; v2 = gA[kf + 2]; v3 = gA[kf + 3]; }
        aF0[0] = lds32(aC + aBase + cA0);            // t=0 rows, k0-15
        aF0[1] = lds32(aC + aBase + 512 + cA0);      // rows+8
        aF0[2] = lds32(aC + aBase + cB0);            // k+16
        aF0[3] = lds32(aC + aBase + 512 + cB0);
        aF1[0] = lds32(aC + aBase + 1024 + cA0);     // t=1
        aF1[1] = lds32(aC + aBase + 1536 + cA0);
        aF1[2] = lds32(aC + aBase + 1024 + cB0);
        aF1[3] = lds32(aC + aBase + 1536 + cB0);
#pragma unroll
        for (int j = 0; j < 4; j++) {
            bF[j][0] = lds32(bC + bBase + j * 512 + cA0);
            bF[j][1] = lds32(bC + bBase + j * 512 + cB0);
        }
#pragma unroll
        for (int j = 0; j < 4; j++) {
            mma_fp8(c[0][j], aF0, bF[j]);
            mma_fp8(c[1][j], aF1, bF[j]);
        }
        if (more) {
            ssA += sumsq4(v0) + sumsq4(v1) + sumsq4(v2) + sumsq4(v3);
            uint32_t ad = aN + stP0;
            sts8(ad, pack_e4m3(v0), pack_e4m3(v1));
            sts8(ad + 8, pack_e4m3(v2), pack_e4m3(v3));
        }
        // sub1: LDG A phase1; B-frags(j 4..7); 8 MMAs
        if (more) { v0 = gA[kf + 4]; v1 = gA[kf + 5]; v2 = gA[kf + 6]; v3 = gA[kf + 7]; }
#pragma unroll
        for (int j = 0; j < 4; j++) {
            bF[j][0] = lds32(bC + bBase + (j + 4) * 512 + cA0);
            bF[j][1] = lds32(bC + bBase + (j + 4) * 512 + cB0);
        }
#pragma unroll
        for (int j = 0; j < 4; j++) {
            mma_fp8(c[0][j + 4], aF0, bF[j]);
            mma_fp8(c[1][j + 4], aF1, bF[j]);
        }
        if (more) {
            ssA += sumsq4(v0) + sumsq4(v1) + sumsq4(v2) + sumsq4(v3);
            uint32_t ad = aN + stP1;
            sts8(ad, pack_e4m3(v0), pack_e4m3(v1));
            sts8(ad + 8, pack_e4m3(v2), pack_e4m3(v3));
        }

        // ======== k32 step s=1 (chunks 2,3) ========
        const uint32_t cA1 = (2u * 16) ^ swF, cB1 = (3u * 16) ^ swF;
        // sub2: LDG B phase0; A-frags + B-frags(j 0..3); 8 MMAs
        if (more) { v0 = gB[kf]; v1 = gB[kf + 1]; v2 = gB[kf + 2]; v3 = gB[kf + 3]; }
        aF0[0] = lds32(aC + aBase + cA1);
        aF0[1] = lds32(aC + aBase + 512 + cA1);
        aF0[2] = lds32(aC + aBase + cB1);
        aF0[3] = lds32(aC + aBase + 512 + cB1);
        aF1[0] = lds32(aC + aBase + 1024 + cA1);
        aF1[1] = lds32(aC + aBase + 1536 + cA1);
        aF1[2] = lds32(aC + aBase + 1024 + cB1);
        aF1[3] = lds32(aC + aBase + 1536 + cB1);
#pragma unroll
        for (int j = 0; j < 4; j++) {
            bF[j][0] = lds32(bC + bBase + j * 512 + cA1);
            bF[j][1] = lds32(bC + bBase + j * 512 + cB1);
        }
#pragma unroll
        for (int j = 0; j < 4; j++) {
            mma_fp8(c[0][j], aF0, bF[j]);
            mma_fp8(c[1][j], aF1, bF[j]);
        }
        if (more) {
            ssB += sumsq4(v0) + sumsq4(v1) + sumsq4(v2) + sumsq4(v3);
            uint32_t ad = bN + stP0;
            sts8(ad, pack_e4m3(v0), pack_e4m3(v1));
            sts8(ad + 8, pack_e4m3(v2), pack_e4m3(v3));
        }
        // sub3: LDG B phase1; B-frags(j 4..7); 8 MMAs
        if (more) { v0 = gB[kf + 4]; v1 = gB[kf + 5]; v2 = gB[kf + 6]; v3 = gB[kf + 7]; }
#pragma unroll
        for (int j = 0; j < 4; j++) {
            bF[j][0] = lds32(bC + bBase + (j + 4) * 512 + cA1);
            bF[j][1] = lds32(bC + bBase + (j + 4) * 512 + cB1);
        }
#pragma unroll
        for (int j = 0; j < 4; j++) {
            mma_fp8(c[0][j + 4], aF0, bF[j]);
            mma_fp8(c[1][j + 4], aF1, bF[j]);
        }
        if (more) {
            ssB += sumsq4(v0) + sumsq4(v1) + sumsq4(v2) + sumsq4(v3);
            uint32_t ad = bN + stP1;
            sts8(ad, pack_e4m3(v0), pack_e4m3(v1));
            sts8(ad + 8, pack_e4m3(v2), pack_e4m3(v3));
            __syncthreads();
        }
    }

    // ---- publish inverse norms (2 threads/row; combine halves via xor 1) ----
    ssA += __shfl_xor_sync(0xFFFFFFFFu, ssA, 1);
    ssB += __shfl_xor_sync(0xFFFFFFFFu, ssB, 1);
    if (h == 0) {
        sRA[r] = SCALE_F / fmaxf(sqrtf(ssA), 1e-12f);
        sRB[r] = 1.0f / fmaxf(sqrtf(ssB), 1e-12f);
    }
    __syncthreads();

    // ---------------- epilogue: scale by rinvA*rinvB, exp, store E ------------
    const int qrow = lane >> 2;
    const int qcol = lane & 3;
#pragma unroll
    for (int t = 0; t < 2; t++) {
        const int row = wm + t * 16 + qrow;
        const float ra0 = sRA[row];
        const float ra1 = sRA[row + 8];
        float* o0 = outA + ((size_t)b * L_ + (m0 + row)) * N_ + (n0 + wn + 2 * qcol);
#pragma unroll
        for (int n = 0; n < 8; n++) {
            const int col = wn + n * 8 + 2 * qcol;
            const float rb0 = sRB[col];
            const float rb1 = sRB[col + 1];
            float e0 = __expf(c[t][n][0] * ra0 * rb0);
            float e1 = __expf(c[t][n][1] * ra0 * rb1);
            float e2 = __expf(c[t][n][2] * ra1 * rb0);
            float e3 = __expf(c[t][n][3] * ra1 * rb1);
            reinterpret_cast<float2*>(o0 + n * 8)[0] = make_float2(e0, e1);
            reinterpret_cast<float2*>(o0 + 8 * N_ + n * 8)[0] = make_float2(e2, e3);
        }
    }
}

// ============================================================================
// Kernel 3: finalize (measured 65.8us, ~3.6TB/s DRAM — near streaming bound).
// ============================================================================
__global__ void __launch_bounds__(256) finalize_kernel(
    float* __restrict__ outA, float* __restrict__ out_sia,
    const float* __restrict__ beta, const int* __restrict__ mask) {
    __shared__ float red[8];
    __shared__ float s_inv[8], s_w[8];
    const int b = blockIdx.y;
    const int chunk = blockIdx.x;            // 0..127 (8 rows each)
    const int tid = threadIdx.x;
    const int lane = tid & 31, w = tid >> 5; // 8 warps

    float bs = 0.0f;
#pragma unroll
    for (int i = 0; i < 4; i++) {
        int l = tid + i * 256;
        bs += beta[b * L_ + l] * (mask[b * L_ + l] != 0 ? 1.0f : 0.0f);
    }
#pragma unroll
    for (int o = 16; o > 0; o >>= 1) bs += __shfl_xor_sync(0xFFFFFFFFu, bs, o);
    if (lane == 0) red[w] = bs;
    __syncthreads();
    const float bdsum = red[0] + red[1] + red[2] + red[3]
                      + red[4] + red[5] + red[6] + red[7];

    const int l = chunk * 8 + w;
    const float4* ep = (const float4*)(outA + ((size_t)b * L_ + l) * N_);
    float rs = 0.0f;
#pragma unroll 4
    for (int i = lane; i < N_ / 4; i += 32) {
        float4 v = ep[i];
        rs += (v.x + v.y) + (v.z + v.w);
    }
#pragma unroll
    for (int o = 16; o > 0; o >>= 1) rs += __shfl_xor_sync(0xFFFFFFFFu, rs, o);
    if (lane == 0) {
        const float m = (mask[b * L_ + l] != 0) ? 1.0f : 0.0f;
        s_inv[w] = (m != 0.0f) ? (1.0f / rs) : 0.0f;
        s_w[w]   = beta[b * L_ + l] * m / (bdsum + 1e-8f);
    }
    __syncthreads();

    float4 acc0 = make_float4(0.f, 0.f, 0.f, 0.f);
    float4 acc1 = acc0, acc2 = acc0, acc3 = acc0;
#pragma unroll
    for (int rr = 0; rr < 8; rr++) {
        const float iv = s_inv[rr];
        const float wt = s_w[rr];
        float4* row = (float4*)(outA + ((size_t)b * L_ + chunk * 8 + rr) * N_);
        float4 e0 = row[tid];
        float4 e1 = row[tid + 256];
        float4 e2 = row[tid + 512];
        float4 e3 = row[tid + 768];
        e0.x *= iv; e0.y *= iv; e0.z *= iv; e0.w *= iv;
        e1.x *= iv; e1.y *= iv; e1.z *= iv; e1.w *= iv;
        e2.x *= iv; e2.y *= iv; e2.z *= iv; e2.w *= iv;
        e3.x *= iv; e3.y *= iv; e3.z *= iv; e3.w *= iv;
        row[tid] = e0; row[tid + 256] = e1; row[tid + 512] = e2; row[tid + 768] = e3;
        acc0.x += wt * e0.x; acc0.y += wt * e0.y; acc0.z += wt * e0.z; acc0.w += wt * e0.w;
        acc1.x += wt * e1.x; acc1.y += wt * e1.y; acc1.z += wt * e1.z; acc1.w += wt * e1.w;
        acc2.x += wt * e2.x; acc2.y += wt * e2.y; acc2.z += wt * e2.z; acc2.w += wt * e2.w;
        acc3.x += wt * e3.x; acc3.y += wt * e3.y; acc3.z += wt * e3.z; acc3.w += wt * e3.w;
    }
    float* sb = out_sia + b * N_;
    atomicAdd(sb + (tid)       * 4 + 0, acc0.x);
    atomicAdd(sb + (tid)       * 4 + 1, acc0.y);
    atomicAdd(sb + (tid)       * 4 + 2, acc0.z);
    atomicAdd(sb + (tid)       * 4 + 3, acc0.w);
    atomicAdd(sb + (tid + 256) * 4 + 0, acc1.x);
    atomicAdd(sb + (tid + 256) * 4 + 1, acc1.y);
    atomicAdd(sb + (tid + 256) * 4 + 2, acc1.z);
    atomicAdd(sb + (tid + 256) * 4 + 3, acc1.w);
    atomicAdd(sb + (tid + 512) * 4 + 0, acc2.x);
    atomicAdd(sb + (tid + 512) * 4 + 1, acc2.y);
    atomicAdd(sb + (tid + 512) * 4 + 2, acc2.z);
    atomicAdd(sb + (tid + 512) * 4 + 3, acc2.w);
    atomicAdd(sb + (tid + 768) * 4 + 0, acc3.x);
    atomicAdd(sb + (tid + 768) * 4 + 1, acc3.y);
    atomicAdd(sb + (tid + 768) * 4 + 2, acc3.z);
    atomicAdd(sb + (tid + 768) * 4 + 3, acc3.w);
}

// ============================================================================
extern "C" void kernel_launch(void* const* d_in, const int* in_sizes, int n_in,
                              void* d_out, int out_size) {
    const float* text = (const float*)d_in[0];
    const float* vis  = (const float*)d_in[1];
    const float* beta = (const float*)d_in[2];
    const int*   mask = (const int*)d_in[3];
    float* out  = (float*)d_out;
    float* outA = out + B_ * N_;   // s_ia first, then A

    // 6-launch pattern keeps the ncu capture slot on the GEMM (index 3).
    zero_sia_kernel<<<(B_ * N_ + 255) / 256, 256>>>(out);   // 0
    pad_kernel<<<1, 32>>>();                                 // 1
    pad_kernel<<<1, 32>>>();                                 // 2
    gemm_exp_kernel<<<dim3(NTILES, L_ / BM, B_), 256>>>(     // 3
        outA, (const float4*)text, (const float4*)vis);
    finalize_kernel<<<dim3(L_ / 8, B_), 256>>>(outA, out, beta, mask);  // 4
    pad_kernel<<<1, 32>>>();                                 // 5
}